// round 7
// baseline (speedup 1.0000x reference)
#include <cuda_runtime.h>
#include <cuda_fp16.h>
#include <cstdint>

// SANet attention, warp-level MMA (base PTX). R7: fp16 main term +
// fp8(e4m3) k-concat cross term for both GEMMs; online softmax.

namespace {
constexpr int HW = 4096, BQ = 128, NKT = 32, NT = 512;
constexpr int SK_ST = 0, SV_ST = 32768, BUF0 = 65536;
constexpr int OFF_KH = 0;           // fp16 K [128k][72e] 144B rows
constexpr int OFF_K8 = 18432;       // fp8  K [128k][144B]: [kl'(64) | kh8(64)]
constexpr int OFF_VH = 36864;       // fp16 V [64c][136e] 272B rows
constexpr int OFF_V8 = 54272;       // fp8  V: 2 khalf planes [64c][144B]: [vl'|vh8]
constexpr int BUF_SZ = 72704;
constexpr int SMEM_BYTES = BUF0 + 2 * BUF_SZ;  // 210944
constexpr float LOG2E = 1.4426950408889634f;
constexpr float INV2K = 1.0f / 2048.0f;
}

__device__ __forceinline__ uint32_t smem_u32(const void* p) {
    uint32_t a;
    asm("{ .reg .u64 t; cvta.to.shared.u64 t, %1; cvt.u32.u64 %0, t; }"
        : "=r"(a) : "l"(p));
    return a;
}
__device__ __forceinline__ void cpa16(uint32_t s, const void* g) {
    asm volatile("cp.async.cg.shared.global [%0], [%1], 16;" :: "r"(s), "l"(g));
}
__device__ __forceinline__ void cpa_commit() {
    asm volatile("cp.async.commit_group;" ::: "memory");
}
__device__ __forceinline__ void cpa_wait0() {
    asm volatile("cp.async.wait_group 0;" ::: "memory");
}
__device__ __forceinline__ void ldsm4(uint32_t a, uint32_t* r) {
    asm volatile("ldmatrix.sync.aligned.m8n8.x4.shared.b16 {%0,%1,%2,%3}, [%4];"
                 : "=r"(r[0]), "=r"(r[1]), "=r"(r[2]), "=r"(r[3]) : "r"(a));
}
__device__ __forceinline__ uint32_t lds32(uint32_t a) {
    uint32_t r;
    asm volatile("ld.shared.b32 %0, [%1];" : "=r"(r) : "r"(a));
    return r;
}
__device__ __forceinline__ void mma_f16(float* d, const uint32_t* a, const uint32_t* b) {
    asm volatile(
        "mma.sync.aligned.m16n8k16.row.col.f32.f16.f16.f32 "
        "{%0,%1,%2,%3}, {%4,%5,%6,%7}, {%8,%9}, {%0,%1,%2,%3};"
        : "+f"(d[0]), "+f"(d[1]), "+f"(d[2]), "+f"(d[3])
        : "r"(a[0]), "r"(a[1]), "r"(a[2]), "r"(a[3]), "r"(b[0]), "r"(b[1]));
}
__device__ __forceinline__ void mma_e4m3(float* d, const uint32_t* a, const uint32_t* b) {
    asm volatile(
        "mma.sync.aligned.m16n8k32.row.col.f32.e4m3.e4m3.f32 "
        "{%0,%1,%2,%3}, {%4,%5,%6,%7}, {%8,%9}, {%0,%1,%2,%3};"
        : "+f"(d[0]), "+f"(d[1]), "+f"(d[2]), "+f"(d[3])
        : "r"(a[0]), "r"(a[1]), "r"(a[2]), "r"(a[3]), "r"(b[0]), "r"(b[1]));
}
__device__ __forceinline__ float ex2f(float x) {
    float y;
    asm("ex2.approx.f32 %0, %1;" : "=f"(y) : "f"(x));
    return y;
}
__device__ __forceinline__ unsigned short e8x2(float hi, float lo) {
    unsigned short r;
    asm("cvt.rn.satfinite.e4m3x2.f32 %0, %1, %2;" : "=h"(r) : "f"(hi), "f"(lo));
    return r;
}
__device__ __forceinline__ uint32_t f16x2(float hi, float lo) {
    uint32_t r;
    asm("cvt.rn.f16x2.f32 %0, %1, %2;" : "=r"(r) : "f"(hi), "f"(lo));
    return r;
}
__device__ __forceinline__ uint32_t prmt(uint32_t a, uint32_t b, uint32_t c) {
    uint32_t r;
    asm("prmt.b32 %0, %1, %2, %3;" : "=r"(r) : "r"(a), "r"(b), "r"(c));
    return r;
}
__device__ __forceinline__ uint32_t pk8(float v0, float v1, float v2, float v3) {
    return (uint32_t)e8x2(v1, v0) | ((uint32_t)e8x2(v3, v2) << 16);
}

// K/Q transpose-convert: stage [64c][128] f32 -> fp16 [k][c] + fp8 concat rows
__device__ __forceinline__ void conv_K(const float* st, char* buf, int tid) {
    const int k = tid & 127, c0 = (tid >> 7) * 16;
    float f[16], r[16];
    uint32_t p16[8];
    #pragma unroll
    for (int j = 0; j < 16; ++j) f[j] = st[(c0 + j) * 128 + k];
    #pragma unroll
    for (int j = 0; j < 16; ++j) {
        const __half h = __float2half_rn(f[j]);
        r[j] = (f[j] - __half2float(h)) * 2048.0f;
        ((__half*)p16)[j] = h;
    }
    char* d16 = buf + OFF_KH + k * 144 + c0 * 2;
    *(uint4*)(d16)      = make_uint4(p16[0], p16[1], p16[2], p16[3]);
    *(uint4*)(d16 + 16) = make_uint4(p16[4], p16[5], p16[6], p16[7]);
    char* d8 = buf + OFF_K8 + k * 144 + c0;
    *(uint4*)(d8) = make_uint4(pk8(r[0], r[1], r[2], r[3]), pk8(r[4], r[5], r[6], r[7]),
                               pk8(r[8], r[9], r[10], r[11]), pk8(r[12], r[13], r[14], r[15]));
    *(uint4*)(d8 + 64) = make_uint4(pk8(f[0], f[1], f[2], f[3]), pk8(f[4], f[5], f[6], f[7]),
                                    pk8(f[8], f[9], f[10], f[11]), pk8(f[12], f[13], f[14], f[15]));
}
// V convert: stage [64c][128k] f32 -> fp16 [c][k] + fp8 khalf planes
__device__ __forceinline__ void conv_V(const float* st, char* buf, int tid) {
    const int c = tid >> 3, kq = (tid & 7) * 16;
    float f[16], r[16];
    uint32_t p16[8];
    #pragma unroll
    for (int j = 0; j < 4; ++j)
        *(float4*)(f + 4 * j) = *(const float4*)(st + c * 128 + kq + 4 * j);
    #pragma unroll
    for (int j = 0; j < 16; ++j) {
        const __half h = __float2half_rn(f[j]);
        r[j] = (f[j] - __half2float(h)) * 2048.0f;
        ((__half*)p16)[j] = h;
    }
    char* d16 = buf + OFF_VH + c * 272 + kq * 2;
    *(uint4*)(d16)      = make_uint4(p16[0], p16[1], p16[2], p16[3]);
    *(uint4*)(d16 + 16) = make_uint4(p16[4], p16[5], p16[6], p16[7]);
    char* d8 = buf + OFF_V8 + (kq >> 6) * 9216 + c * 144 + (kq & 63);
    *(uint4*)(d8) = make_uint4(pk8(r[0], r[1], r[2], r[3]), pk8(r[4], r[5], r[6], r[7]),
                               pk8(r[8], r[9], r[10], r[11]), pk8(r[12], r[13], r[14], r[15]));
    *(uint4*)(d8 + 64) = make_uint4(pk8(f[0], f[1], f[2], f[3]), pk8(f[4], f[5], f[6], f[7]),
                                    pk8(f[8], f[9], f[10], f[11]), pk8(f[12], f[13], f[14], f[15]));
}

// build fp8 A-frag (4 regs) for one k32 step from packed row-pairs arr[base..base+3]
__device__ __forceinline__ void build_a8(const uint32_t* arr, int base, int lane,
                                         uint32_t* out) {
    const int t = lane & 3;
    const bool odd = t & 1;
    const uint32_t sG = odd ? 0x1054u : 0x5410u;
    const uint32_t sH = odd ? 0x3276u : 0x7632u;
    uint32_t QG[4], QH[4];
    #pragma unroll
    for (int j = 0; j < 4; ++j) {
        const uint32_t own = arr[base + j];
        const uint32_t prt = __shfl_xor_sync(0xffffffffu, own, 1);
        QG[j] = prmt(own, prt, sG);
        QH[j] = prmt(own, prt, sH);
    }
    const int src = (lane & ~3) | (2 * (t & 1) + (t >> 1));
    out[0] = __shfl_sync(0xffffffffu, QG[t & 1], src);
    out[1] = __shfl_sync(0xffffffffu, QH[t & 1], src);
    out[2] = __shfl_sync(0xffffffffu, QG[2 + (t & 1)], src);
    out[3] = __shfl_sync(0xffffffffu, QH[2 + (t & 1)], src);
}

__global__ __launch_bounds__(NT, 1)
void sanet_r7(const float* __restrict__ content,
              const float* __restrict__ content_s,
              const float* __restrict__ style,
              float* __restrict__ out)
{
    extern __shared__ __align__(16) char smc[];
    const uint32_t sb = smem_u32(smc);
    float* stK = (float*)(smc + SK_ST);
    float* stV = (float*)(smc + SV_ST);

    const int tid = threadIdx.x;
    const int lane = tid & 31;
    const int qblk = (tid >> 5) & 7;
    const int khalf = tid >> 8;     // warps 0-7: khalf 0; 8-15: khalf 1
    const int g = lane >> 2, t = lane & 3;
    const int b = blockIdx.y;
    const int q0 = blockIdx.x * BQ;

    const float* Qg = content   + (size_t)b * 64 * HW;
    const float* Kg = content_s + (size_t)b * 64 * HW;
    const float* Vg = style     + (size_t)b * 64 * HW;
    float* outg     = out       + (size_t)b * 128 * HW;

    // ---- stage Q ----
    #pragma unroll
    for (int j = 0; j < 4; ++j) {
        const int idx = tid + 512 * j;
        const int c = idx >> 5, kc = idx & 31;
        cpa16(sb + SK_ST + c * 512 + kc * 16, Qg + (size_t)c * HW + q0 + kc * 4);
    }
    cpa_commit();
    cpa_wait0();
    __syncthreads();

    {   // content passthrough
        const int q = tid & 127;
        const int c0 = (tid >> 7) * 16;
        #pragma unroll
        for (int j = 0; j < 16; ++j)
            outg[(size_t)(c0 + j) * HW + q0 + q] = stK[(c0 + j) * 128 + q];
    }

    // ---- persistent Q fragments from stage ----
    uint32_t qa16[4][4], qa8[4][4];
    {
        const int qA = qblk * 16 + g;
        #pragma unroll
        for (int s = 0; s < 4; ++s) {
            const int ch = 16 * s + 2 * t;
            qa16[s][0] = f16x2(stK[(ch + 1) * 128 + qA],     stK[ch * 128 + qA]);
            qa16[s][1] = f16x2(stK[(ch + 1) * 128 + qA + 8], stK[ch * 128 + qA + 8]);
            qa16[s][2] = f16x2(stK[(ch + 9) * 128 + qA],     stK[(ch + 8) * 128 + qA]);
            qa16[s][3] = f16x2(stK[(ch + 9) * 128 + qA + 8], stK[(ch + 8) * 128 + qA + 8]);
        }
        #pragma unroll
        for (int s = 0; s < 4; ++s) {
            const bool hi = (s < 2);
            #pragma unroll
            for (int half = 0; half < 2; ++half) {      // a0/a1 then a2/a3
                const int ch = 32 * s + 16 * half + 4 * t - (hi ? 0 : 64);
                #pragma unroll
                for (int row = 0; row < 2; ++row) {
                    float v[4];
                    #pragma unroll
                    for (int j = 0; j < 4; ++j) {
                        float q = stK[(ch + j) * 128 + qA + 8 * row];
                        if (!hi) q = (q - __half2float(__float2half_rn(q))) * 2048.0f;
                        v[j] = q;
                    }
                    qa8[s][half * 2 + row] = pk8(v[0], v[1], v[2], v[3]);
                }
            }
        }
    }
    __syncthreads();

    // ---- prime tile 0 ----
    #pragma unroll
    for (int j = 0; j < 4; ++j) {
        const int idx = tid + 512 * j;
        const int c = idx >> 5, kc = idx & 31;
        cpa16(sb + SK_ST + c * 512 + kc * 16, Kg + (size_t)c * HW + kc * 4);
        cpa16(sb + SV_ST + c * 512 + kc * 16, Vg + (size_t)c * HW + kc * 4);
    }
    cpa_commit();
    cpa_wait0();
    __syncthreads();
    conv_K(stK, smc + BUF0, tid);
    conv_V(stV, smc + BUF0, tid);
    __syncthreads();

    float oAcc[8][4];
    #pragma unroll
    for (int nt = 0; nt < 8; ++nt)
        #pragma unroll
        for (int i = 0; i < 4; ++i) oAcc[nt][i] = 0.0f;
    float m0 = -1e30f, m1 = -1e30f, l0 = 0.0f, l1 = 0.0f;

    const uint32_t laneLD = (uint32_t)(lane & 7) * 144u + (uint32_t)(lane >> 3) * 16u;
    const uint32_t laneLDV = (uint32_t)(lane & 7) * 272u + (uint32_t)(lane >> 3) * 16u;

    for (int kt = 0; kt < NKT; ++kt) {
        if (kt + 1 < NKT) {
            const int kk1 = (kt + 1) * 128;
            #pragma unroll
            for (int j = 0; j < 4; ++j) {
                const int idx = tid + 512 * j;
                const int c = idx >> 5, kc = idx & 31;
                cpa16(sb + SK_ST + c * 512 + kc * 16, Kg + (size_t)c * HW + kk1 + kc * 4);
                cpa16(sb + SV_ST + c * 512 + kc * 16, Vg + (size_t)c * HW + kk1 + kc * 4);
            }
            cpa_commit();
        }

        const uint32_t bufb = sb + BUF0 + (uint32_t)(kt & 1) * BUF_SZ;
        const uint32_t khB = bufb + OFF_KH + (uint32_t)khalf * 9216u + laneLD;
        const uint32_t k8B = bufb + OFF_K8 + (uint32_t)khalf * 9216u +
                             (uint32_t)g * 144u + (uint32_t)t * 4u;

        // ---- GEMM1: S = Q.K^T (fp8 cross then fp16 main) ----
        float sAcc[8][4];
        #pragma unroll
        for (int nt = 0; nt < 8; ++nt) {
            float c8[4] = {0.0f, 0.0f, 0.0f, 0.0f};
            #pragma unroll
            for (int s = 0; s < 4; ++s) {
                uint32_t bb[2];
                bb[0] = lds32(k8B + nt * 1152u + s * 32u);
                bb[1] = lds32(k8B + nt * 1152u + s * 32u + 16u);
                mma_e4m3(c8, qa8[s], bb);
            }
            #pragma unroll
            for (int i = 0; i < 4; ++i) sAcc[nt][i] = c8[i] * INV2K;
            uint32_t ra[4], rb[4];
            ldsm4(khB + nt * 1152u, ra);
            ldsm4(khB + nt * 1152u + 64u, rb);
            mma_f16(sAcc[nt], qa16[0], ra);
            mma_f16(sAcc[nt], qa16[1], ra + 2);
            mma_f16(sAcc[nt], qa16[2], rb);
            mma_f16(sAcc[nt], qa16[3], rb + 2);
        }

        // ---- online softmax ----
        float tm0 = -1e30f, tm1 = -1e30f;
        #pragma unroll
        for (int nt = 0; nt < 8; ++nt) {
            tm0 = fmaxf(tm0, fmaxf(sAcc[nt][0], sAcc[nt][1]));
            tm1 = fmaxf(tm1, fmaxf(sAcc[nt][2], sAcc[nt][3]));
        }
        tm0 = fmaxf(tm0, __shfl_xor_sync(0xffffffffu, tm0, 1));
        tm0 = fmaxf(tm0, __shfl_xor_sync(0xffffffffu, tm0, 2));
        tm1 = fmaxf(tm1, __shfl_xor_sync(0xffffffffu, tm1, 1));
        tm1 = fmaxf(tm1, __shfl_xor_sync(0xffffffffu, tm1, 2));
        const float mn0 = fmaxf(m0, tm0), mn1 = fmaxf(m1, tm1);
        const float sc0 = ex2f((m0 - mn0) * LOG2E);
        const float sc1 = ex2f((m1 - mn1) * LOG2E);
        m0 = mn0; m1 = mn1; l0 *= sc0; l1 *= sc1;
        #pragma unroll
        for (int nt = 0; nt < 8; ++nt) {
            oAcc[nt][0] *= sc0; oAcc[nt][1] *= sc0;
            oAcc[nt][2] *= sc1; oAcc[nt][3] *= sc1;
        }
        const float mL0 = mn0 * LOG2E, mL1 = mn1 * LOG2E;

        uint32_t pp16[8], qq16[8], P32[8], PL32[8];
        float r0 = 0.0f, r1 = 0.0f;
        #pragma unroll
        for (int nt = 0; nt < 8; ++nt) {
            const float p0 = ex2f(fmaf(sAcc[nt][0], LOG2E, -mL0));
            const float p1 = ex2f(fmaf(sAcc[nt][1], LOG2E, -mL0));
            const float p2 = ex2f(fmaf(sAcc[nt][2], LOG2E, -mL1));
            const float p3 = ex2f(fmaf(sAcc[nt][3], LOG2E, -mL1));
            r0 += p0 + p1; r1 += p2 + p3;
            pp16[nt] = f16x2(p1, p0);
            qq16[nt] = f16x2(p3, p2);
            const __half2 ha = *(__half2*)&pp16[nt];
            const __half2 hb = *(__half2*)&qq16[nt];
            const float e0 = (p0 - __half2float(__low2half(ha)))  * 2048.0f;
            const float e1 = (p1 - __half2float(__high2half(ha))) * 2048.0f;
            const float e2 = (p2 - __half2float(__low2half(hb)))  * 2048.0f;
            const float e3 = (p3 - __half2float(__high2half(hb))) * 2048.0f;
            P32[nt]  = (uint32_t)e8x2(p1, p0) | ((uint32_t)e8x2(p3, p2) << 16);
            PL32[nt] = (uint32_t)e8x2(e1, e0) | ((uint32_t)e8x2(e3, e2) << 16);
        }
        r0 += __shfl_xor_sync(0xffffffffu, r0, 1);
        r0 += __shfl_xor_sync(0xffffffffu, r0, 2);
        r1 += __shfl_xor_sync(0xffffffffu, r1, 1);
        r1 += __shfl_xor_sync(0xffffffffu, r1, 2);
        l0 += r0; l1 += r1;

        // ---- P fp8 A-fragments (in-register shuffles) ----
        uint32_t a8[4][4];
        build_a8(P32, 0, lane, a8[0]);
        build_a8(P32, 4, lane, a8[1]);
        build_a8(PL32, 0, lane, a8[2]);
        build_a8(PL32, 4, lane, a8[3]);

        // ---- GEMM2: O += P.V^T ----
        const uint32_t vhB = bufb + OFF_VH + (uint32_t)khalf * 128u + laneLDV;
        const uint32_t v8B = bufb + OFF_V8 + (uint32_t)khalf * 9216u +
                             (uint32_t)g * 144u + (uint32_t)t * 4u;
        #pragma unroll
        for (int nc = 0; nc < 8; ++nc) {
            float o8[4] = {0.0f, 0.0f, 0.0f, 0.0f};
            #pragma unroll
            for (int s = 0; s < 4; ++s) {
                uint32_t bb[2];
                bb[0] = lds32(v8B + nc * 1152u + s * 32u);
                bb[1] = lds32(v8B + nc * 1152u + s * 32u + 16u);
                mma_e4m3(o8, a8[s], bb);
            }
            #pragma unroll
            for (int i = 0; i < 4; ++i) oAcc[nc][i] = fmaf(o8[i], INV2K, oAcc[nc][i]);
            uint32_t ra[4], rb[4];
            ldsm4(vhB + nc * 2176u, ra);
            ldsm4(vhB + nc * 2176u + 64u, rb);
            uint32_t a0[4] = {pp16[0], qq16[0], pp16[1], qq16[1]};
            uint32_t a1[4] = {pp16[2], qq16[2], pp16[3], qq16[3]};
            uint32_t a2[4] = {pp16[4], qq16[4], pp16[5], qq16[5]};
            uint32_t a3[4] = {pp16[6], qq16[6], pp16[7], qq16[7]};
            mma_f16(oAcc[nc], a0, ra);
            mma_f16(oAcc[nc], a1, ra + 2);
            mma_f16(oAcc[nc], a2, rb);
            mma_f16(oAcc[nc], a3, rb + 2);
        }

        if (kt + 1 < NKT) {
            cpa_wait0();
            __syncthreads();
            char* dst = smc + BUF0 + ((kt + 1) & 1) * BUF_SZ;
            conv_K(stK, dst, tid);
            conv_V(stV, dst, tid);
        }
        __syncthreads();
    }

    // ---- epilogue: merge khalf partials (max-aware), normalize, store ----
    __syncthreads();
    float* redO = (float*)smc;              // 8*32*32 floats = 32KB
    float* redM = (float*)(smc + 32768);    // 8*32*4 floats
    if (khalf == 1) {
        float* d = redO + (qblk * 32 + lane) * 32;
        #pragma unroll
        for (int nt = 0; nt < 8; ++nt)
            #pragma unroll
            for (int i = 0; i < 4; ++i) d[nt * 4 + i] = oAcc[nt][i];
        float* dm = redM + (qblk * 32 + lane) * 4;
        dm[0] = m0; dm[1] = m1; dm[2] = l0; dm[3] = l1;
    }
    __syncthreads();
    if (khalf == 0) {
        const float* src = redO + (qblk * 32 + lane) * 32;
        const float* sm2 = redM + (qblk * 32 + lane) * 4;
        const float mB0 = sm2[0], mB1 = sm2[1], lB0 = sm2[2], lB1 = sm2[3];
        const float M0 = fmaxf(m0, mB0), M1 = fmaxf(m1, mB1);
        const float fA0 = ex2f((m0 - M0) * LOG2E), fB0 = ex2f((mB0 - M0) * LOG2E);
        const float fA1 = ex2f((m1 - M1) * LOG2E), fB1 = ex2f((mB1 - M1) * LOG2E);
        const float inv0 = 1.0f / (l0 * fA0 + lB0 * fB0);
        const float inv1 = 1.0f / (l1 * fA1 + lB1 * fB1);
        const int qa = q0 + qblk * 16 + g;
        const int qb = qa + 8;
        #pragma unroll
        for (int nt = 0; nt < 8; ++nt) {
            const int c = nt * 8 + 2 * t;
            outg[(size_t)(64 + c) * HW + qa] =
                (oAcc[nt][0] * fA0 + src[nt * 4 + 0] * fB0) * inv0;
            outg[(size_t)(65 + c) * HW + qa] =
                (oAcc[nt][1] * fA0 + src[nt * 4 + 1] * fB0) * inv0;
            outg[(size_t)(64 + c) * HW + qb] =
                (oAcc[nt][2] * fA1 + src[nt * 4 + 2] * fB1) * inv1;
            outg[(size_t)(65 + c) * HW + qb] =
                (oAcc[nt][3] * fA1 + src[nt * 4 + 3] * fB1) * inv1;
        }
    }
}

extern "C" void kernel_launch(void* const* d_in, const int* in_sizes, int n_in,
                              void* d_out, int out_size)
{
    const float* content   = (const float*)d_in[0];
    const float* content_s = (const float*)d_in[1];
    const float* style     = (const float*)d_in[2];
    float* out = (float*)d_out;

    cudaFuncSetAttribute(sanet_r7, cudaFuncAttributeMaxDynamicSharedMemorySize,
                         SMEM_BYTES);
    dim3 grid(HW / BQ, 4);
    sanet_r7<<<grid, NT, SMEM_BYTES>>>(content, content_s, style, out);
}

// round 8
// speedup vs baseline: 1.8080x; 1.8080x over previous
#include <cuda_runtime.h>
#include <cuda_bf16.h>
#include <cstdint>

// SANet attention, warp-level bf16 HMMA (base PTX), R8:
// pre-pass kernel converts all K/V to bf16 hi/lo tile blocks in global scratch
// (exact SMEM layout); main kernel cp.asyncs finished tiles -> loop is
// GEMM1 / softmax / GEMM2 only. Math identical to R5 (3-term bf16 split,
// no-max softmax).

namespace {
constexpr int HW  = 4096;
constexpr int BQ  = 128;
constexpr int NKT = 32;
constexpr int NT  = 512;     // 16 warps: (qblk 0..7) x (khalf 0..1)

constexpr int QK_STR = 72;   // bf16 elems per K row (144 B)
constexpr int V_STR  = 136;  // bf16 elems per V row (272 B)

constexpr int KPLANE = 128 * 144;            // 18432 B per K plane
constexpr int VPLANE = 64 * 272;             // 17408 B per V plane
constexpr int OFF_VHI = 2 * KPLANE;          // V planes after K hi/lo
constexpr int BUF_SZ  = 2 * KPLANE + 2 * VPLANE;  // 71680 B per tile block
constexpr int SMEM_BYTES = 2 * BUF_SZ;       // 143360 B (double buffer)
constexpr int KLO_E = KPLANE / 2;            // elem offset hi->lo
constexpr int VLO_E = VPLANE / 2;
constexpr int NCHUNK = BUF_SZ / 16;          // 4480 16B chunks per tile
}

__device__ __align__(16) char g_kv[(size_t)4 * NKT * BUF_SZ];   // 9.2 MB scratch

__device__ __forceinline__ uint32_t smem_u32(const void* p) {
    uint32_t a;
    asm("{ .reg .u64 t; cvta.to.shared.u64 t, %1; cvt.u32.u64 %0, t; }"
        : "=r"(a) : "l"(p));
    return a;
}
__device__ __forceinline__ void cpa16(uint32_t s, const void* g) {
    asm volatile("cp.async.cg.shared.global [%0], [%1], 16;" :: "r"(s), "l"(g));
}
__device__ __forceinline__ void cpa_commit() {
    asm volatile("cp.async.commit_group;" ::: "memory");
}
__device__ __forceinline__ void cpa_wait0() {
    asm volatile("cp.async.wait_group 0;" ::: "memory");
}
__device__ __forceinline__ void ldsm4(uint32_t a, uint32_t* r) {
    asm volatile("ldmatrix.sync.aligned.m8n8.x4.shared.b16 {%0,%1,%2,%3}, [%4];"
                 : "=r"(r[0]), "=r"(r[1]), "=r"(r[2]), "=r"(r[3]) : "r"(a));
}
__device__ __forceinline__ void mma_bf16(float* d, const uint32_t* a,
                                         const uint32_t* b) {
    asm volatile(
        "mma.sync.aligned.m16n8k16.row.col.f32.bf16.bf16.f32 "
        "{%0,%1,%2,%3}, {%4,%5,%6,%7}, {%8,%9}, {%0,%1,%2,%3};"
        : "+f"(d[0]), "+f"(d[1]), "+f"(d[2]), "+f"(d[3])
        : "r"(a[0]), "r"(a[1]), "r"(a[2]), "r"(a[3]), "r"(b[0]), "r"(b[1]));
}
__device__ __forceinline__ void split_pack(float x, float y,
                                           uint32_t& hi, uint32_t& lo) {
    __nv_bfloat16 xh = __float2bfloat16_rn(x);
    __nv_bfloat16 yh = __float2bfloat16_rn(y);
    __nv_bfloat16 xl = __float2bfloat16_rn(x - __bfloat162float(xh));
    __nv_bfloat16 yl = __float2bfloat16_rn(y - __bfloat162float(yh));
    hi = (uint32_t)__bfloat16_as_ushort(xh) |
         ((uint32_t)__bfloat16_as_ushort(yh) << 16);
    lo = (uint32_t)__bfloat16_as_ushort(xl) |
         ((uint32_t)__bfloat16_as_ushort(yl) << 16);
}

// ---------------- pre-pass: K/V fp32 -> bf16 hi/lo tile blocks ----------------
__global__ __launch_bounds__(512)
void sanet_prepass(const float* __restrict__ Ksrc, const float* __restrict__ Vsrc)
{
    const int kt = blockIdx.x, b = blockIdx.y, tid = threadIdx.x;
    char* dst = g_kv + (size_t)(b * NKT + kt) * BUF_SZ;
    const float* Kg = Ksrc + (size_t)b * 64 * HW + kt * 128;
    const float* Vg = Vsrc + (size_t)b * 64 * HW + kt * 128;

    {   // K -> [k][c] planes (transpose), 144B rows
        const int k = tid & 127, c0 = (tid >> 7) * 16;
        float f[16];
        uint32_t h[8], l[8];
        #pragma unroll
        for (int j = 0; j < 16; ++j) f[j] = Kg[(size_t)(c0 + j) * HW + k];
        #pragma unroll
        for (int j = 0; j < 8; ++j) split_pack(f[2 * j], f[2 * j + 1], h[j], l[j]);
        char* d = dst + k * 144 + c0 * 2;
        *(uint4*)(d)                = make_uint4(h[0], h[1], h[2], h[3]);
        *(uint4*)(d + 16)           = make_uint4(h[4], h[5], h[6], h[7]);
        *(uint4*)(d + KPLANE)       = make_uint4(l[0], l[1], l[2], l[3]);
        *(uint4*)(d + KPLANE + 16)  = make_uint4(l[4], l[5], l[6], l[7]);
    }
    {   // V -> [c][k] planes (no transpose), 272B rows
        const int c = tid >> 3, kq = (tid & 7) * 16;
        float f[16];
        uint32_t h[8], l[8];
        #pragma unroll
        for (int j = 0; j < 4; ++j)
            *(float4*)(f + 4 * j) = *(const float4*)(Vg + (size_t)c * HW + kq + 4 * j);
        #pragma unroll
        for (int j = 0; j < 8; ++j) split_pack(f[2 * j], f[2 * j + 1], h[j], l[j]);
        char* d = dst + OFF_VHI + c * 272 + kq * 2;
        *(uint4*)(d)                = make_uint4(h[0], h[1], h[2], h[3]);
        *(uint4*)(d + 16)           = make_uint4(h[4], h[5], h[6], h[7]);
        *(uint4*)(d + VPLANE)       = make_uint4(l[0], l[1], l[2], l[3]);
        *(uint4*)(d + VPLANE + 16)  = make_uint4(l[4], l[5], l[6], l[7]);
    }
}

// ---------------- main kernel ----------------
__global__ __launch_bounds__(NT, 1)
void sanet_main(const float* __restrict__ content, float* __restrict__ out)
{
    extern __shared__ __align__(16) char smc[];
    const uint32_t sb = smem_u32(smc);

    const int tid   = threadIdx.x;
    const int wid   = tid >> 5;
    const int lane  = tid & 31;
    const int qblk  = wid & 7;
    const int khalf = wid >> 3;
    const int g     = lane >> 2;
    const int t     = lane & 3;
    const int b     = blockIdx.y;
    const int q0    = blockIdx.x * BQ;

    const float* Qg = content + (size_t)b * 64 * HW;
    float* outg     = out     + (size_t)b * 128 * HW;
    const char* kvb = g_kv + (size_t)b * NKT * BUF_SZ;

    const uint32_t laneK = (uint32_t)(lane & 7) * 144u +
                           (uint32_t)((lane >> 3) & 1) * 16u +
                           (uint32_t)((lane >> 4) & 1) * (uint32_t)KPLANE;
    const uint32_t laneV = (uint32_t)(lane & 7) * 272u +
                           (uint32_t)((lane >> 3) & 1) * 16u +
                           (uint32_t)((lane >> 4) & 1) * (uint32_t)VPLANE;

    // ---- prologue: stage Q fp32 into buf0 area ----
    float* stQ = (float*)smc;   // [64c][128q] fp32, 32 KB (before tile 0 load)
    #pragma unroll
    for (int j = 0; j < 4; ++j) {
        const int idx = tid + 512 * j;
        const int c = idx >> 5, kc = idx & 31;
        cpa16(sb + c * 512 + kc * 16, Qg + (size_t)c * HW + q0 + kc * 4);
    }
    cpa_commit();
    cpa_wait0();
    __syncthreads();

    {   // content passthrough (coalesced)
        const int q = tid & 127;
        const int c0 = (tid >> 7) * 16;
        #pragma unroll
        for (int j = 0; j < 16; ++j)
            outg[(size_t)(c0 + j) * HW + q0 + q] = stQ[(c0 + j) * 128 + q];
    }

    // ---- persistent Q A-fragments, split in registers from fp32 stage ----
    uint32_t qa_hi[4][4], qa_lo[4][4];
    {
        const int qA = qblk * 16 + g;
        #pragma unroll
        for (int s = 0; s < 4; ++s) {
            const int ch = 16 * s + 2 * t;
            split_pack(stQ[ch * 128 + qA],           stQ[(ch + 1) * 128 + qA],
                       qa_hi[s][0], qa_lo[s][0]);
            split_pack(stQ[ch * 128 + qA + 8],       stQ[(ch + 1) * 128 + qA + 8],
                       qa_hi[s][1], qa_lo[s][1]);
            split_pack(stQ[(ch + 8) * 128 + qA],     stQ[(ch + 9) * 128 + qA],
                       qa_hi[s][2], qa_lo[s][2]);
            split_pack(stQ[(ch + 8) * 128 + qA + 8], stQ[(ch + 9) * 128 + qA + 8],
                       qa_hi[s][3], qa_lo[s][3]);
        }
    }
    __syncthreads();   // stage reads done before tile 0 overwrites buf0

    // ---- prime tile 0 ----
    for (int j = tid; j < NCHUNK; j += NT)
        cpa16(sb + j * 16, kvb + j * 16);
    cpa_commit();
    cpa_wait0();
    __syncthreads();

    float oAcc[8][4];
    #pragma unroll
    for (int nt = 0; nt < 8; ++nt)
        #pragma unroll
        for (int i = 0; i < 4; ++i) oAcc[nt][i] = 0.0f;
    float l0sum = 0.0f, l1sum = 0.0f;

    for (int kt = 0; kt < NKT; ++kt) {
        // prefetch tile kt+1 into the other buffer (overlaps the GEMMs)
        if (kt + 1 < NKT) {
            const uint32_t dst = sb + (uint32_t)((kt + 1) & 1) * BUF_SZ;
            const char* src = kvb + (size_t)(kt + 1) * BUF_SZ;
            for (int j = tid; j < NCHUNK; j += NT)
                cpa16(dst + j * 16, src + j * 16);
            cpa_commit();
        }

        const uint32_t bufb = sb + (uint32_t)(kt & 1) * BUF_SZ;
        const uint32_t kaddr = bufb + (uint32_t)khalf * (64u * 144u) + laneK;
        const uint32_t vaddr = bufb + OFF_VHI + (uint32_t)khalf * 128u + laneV;

        // ---- GEMM1: S[16q x 64k] = Q.K^T (3-term bf16 split) ----
        float sAcc[8][4];
        #pragma unroll
        for (int nt = 0; nt < 8; ++nt)
            #pragma unroll
            for (int i = 0; i < 4; ++i) sAcc[nt][i] = 0.0f;

        #pragma unroll
        for (int s = 0; s < 4; ++s) {
            #pragma unroll
            for (int np = 0; np < 4; ++np) {
                uint32_t ra[4], rb[4];
                ldsm4(kaddr + (2 * np) * 1152u + s * 32u, ra);
                ldsm4(kaddr + (2 * np + 1) * 1152u + s * 32u, rb);
                mma_bf16(sAcc[2 * np],     qa_hi[s], ra);
                mma_bf16(sAcc[2 * np + 1], qa_hi[s], rb);
                mma_bf16(sAcc[2 * np],     qa_hi[s], ra + 2);
                mma_bf16(sAcc[2 * np + 1], qa_hi[s], rb + 2);
                mma_bf16(sAcc[2 * np],     qa_lo[s], ra);
                mma_bf16(sAcc[2 * np + 1], qa_lo[s], rb);
            }
        }

        // ---- softmax (no max shift) + in-place P fragment build ----
        float* flat = &sAcc[0][0];
        float r0 = 0.0f, r1 = 0.0f;
        #pragma unroll
        for (int s = 0; s < 4; ++s) {
            float p[8];
            #pragma unroll
            for (int i = 0; i < 8; ++i) p[i] = __expf(flat[8 * s + i]);
            r0 += (p[0] + p[1]) + (p[4] + p[5]);
            r1 += (p[2] + p[3]) + (p[6] + p[7]);
            uint32_t h01, l01, h23, l23, h45, l45, h67, l67;
            split_pack(p[0], p[1], h01, l01);
            split_pack(p[2], p[3], h23, l23);
            split_pack(p[4], p[5], h45, l45);
            split_pack(p[6], p[7], h67, l67);
            flat[8 * s + 0] = __uint_as_float(h01);
            flat[8 * s + 1] = __uint_as_float(h23);
            flat[8 * s + 2] = __uint_as_float(h45);
            flat[8 * s + 3] = __uint_as_float(h67);
            flat[8 * s + 4] = __uint_as_float(l01);
            flat[8 * s + 5] = __uint_as_float(l23);
            flat[8 * s + 6] = __uint_as_float(l45);
            flat[8 * s + 7] = __uint_as_float(l67);
        }
        r0 += __shfl_xor_sync(0xffffffffu, r0, 1);
        r0 += __shfl_xor_sync(0xffffffffu, r0, 2);
        r1 += __shfl_xor_sync(0xffffffffu, r1, 1);
        r1 += __shfl_xor_sync(0xffffffffu, r1, 2);
        l0sum += r0;
        l1sum += r1;

        // ---- GEMM2: O[16q x 64c] += P.V^T (partial over this key half) ----
        #pragma unroll
        for (int s = 0; s < 4; ++s) {
            uint32_t ah[4], al[4];
            #pragma unroll
            for (int i = 0; i < 4; ++i) {
                ah[i] = __float_as_uint(flat[8 * s + i]);
                al[i] = __float_as_uint(flat[8 * s + 4 + i]);
            }
            #pragma unroll
            for (int np = 0; np < 4; ++np) {
                uint32_t ra[4], rb[4];
                ldsm4(vaddr + (2 * np) * 2176u + s * 32u, ra);
                ldsm4(vaddr + (2 * np + 1) * 2176u + s * 32u, rb);
                mma_bf16(oAcc[2 * np],     ah, ra);
                mma_bf16(oAcc[2 * np + 1], ah, rb);
                mma_bf16(oAcc[2 * np],     ah, ra + 2);
                mma_bf16(oAcc[2 * np + 1], ah, rb + 2);
                mma_bf16(oAcc[2 * np],     al, ra);
                mma_bf16(oAcc[2 * np + 1], al, rb);
            }
        }

        if (kt + 1 < NKT) cpa_wait0();
        __syncthreads();   // all reads of buf[kt&1] done; tile kt+1 visible
    }

    // ---- epilogue: pair-reduce khalf partials via SMEM, normalize, store ----
    float* redO = (float*)smc;             // 8 warps * 32 lanes * 32 floats
    float* redL = (float*)(smc + 32768);
    if (khalf == 1) {
        float* dst = redO + (qblk * 32 + lane) * 32;
        #pragma unroll
        for (int nt = 0; nt < 8; ++nt)
            #pragma unroll
            for (int i = 0; i < 4; ++i) dst[nt * 4 + i] = oAcc[nt][i];
        redL[(qblk * 32 + lane) * 2 + 0] = l0sum;
        redL[(qblk * 32 + lane) * 2 + 1] = l1sum;
    }
    __syncthreads();
    if (khalf == 0) {
        const float* src = redO + (qblk * 32 + lane) * 32;
        const float inv0 = 1.0f / (l0sum + redL[(qblk * 32 + lane) * 2 + 0]);
        const float inv1 = 1.0f / (l1sum + redL[(qblk * 32 + lane) * 2 + 1]);
        const int qa = q0 + qblk * 16 + g;
        const int qb = qa + 8;
        #pragma unroll
        for (int nt = 0; nt < 8; ++nt) {
            const int c = nt * 8 + 2 * t;
            outg[(size_t)(64 + c) * HW + qa] = (oAcc[nt][0] + src[nt * 4 + 0]) * inv0;
            outg[(size_t)(65 + c) * HW + qa] = (oAcc[nt][1] + src[nt * 4 + 1]) * inv0;
            outg[(size_t)(64 + c) * HW + qb] = (oAcc[nt][2] + src[nt * 4 + 2]) * inv1;
            outg[(size_t)(65 + c) * HW + qb] = (oAcc[nt][3] + src[nt * 4 + 3]) * inv1;
        }
    }
}

extern "C" void kernel_launch(void* const* d_in, const int* in_sizes, int n_in,
                              void* d_out, int out_size)
{
    const float* content   = (const float*)d_in[0];
    const float* content_s = (const float*)d_in[1];
    const float* style     = (const float*)d_in[2];
    float* out = (float*)d_out;

    cudaFuncSetAttribute(sanet_main, cudaFuncAttributeMaxDynamicSharedMemorySize,
                         SMEM_BYTES);

    dim3 pgrid(NKT, 4);
    sanet_prepass<<<pgrid, 512>>>(content_s, style);

    dim3 grid(HW / BQ, 4);   // 128 CTAs
    sanet_main<<<grid, NT, SMEM_BYTES>>>(content, out);
}

// round 9
// speedup vs baseline: 1.8099x; 1.0010x over previous
#include <cuda_runtime.h>
#include <cuda_bf16.h>
#include <cstdint>

// SANet attention, warp-level bf16 HMMA (base PTX), R8:
// pre-pass kernel converts all K/V to bf16 hi/lo tile blocks in global scratch
// (exact SMEM layout); main kernel cp.asyncs finished tiles -> loop is
// GEMM1 / softmax / GEMM2 only. Math identical to R5 (3-term bf16 split,
// no-max softmax).

namespace {
constexpr int HW  = 4096;
constexpr int BQ  = 128;
constexpr int NKT = 32;
constexpr int NT  = 512;     // 16 warps: (qblk 0..7) x (khalf 0..1)

constexpr int QK_STR = 72;   // bf16 elems per K row (144 B)
constexpr int V_STR  = 136;  // bf16 elems per V row (272 B)

constexpr int KPLANE = 128 * 144;            // 18432 B per K plane
constexpr int VPLANE = 64 * 272;             // 17408 B per V plane
constexpr int OFF_VHI = 2 * KPLANE;          // V planes after K hi/lo
constexpr int BUF_SZ  = 2 * KPLANE + 2 * VPLANE;  // 71680 B per tile block
constexpr int SMEM_BYTES = 2 * BUF_SZ;       // 143360 B (double buffer)
constexpr int KLO_E = KPLANE / 2;            // elem offset hi->lo
constexpr int VLO_E = VPLANE / 2;
constexpr int NCHUNK = BUF_SZ / 16;          // 4480 16B chunks per tile
}

__device__ __align__(16) char g_kv[(size_t)4 * NKT * BUF_SZ];   // 9.2 MB scratch

__device__ __forceinline__ uint32_t smem_u32(const void* p) {
    uint32_t a;
    asm("{ .reg .u64 t; cvta.to.shared.u64 t, %1; cvt.u32.u64 %0, t; }"
        : "=r"(a) : "l"(p));
    return a;
}
__device__ __forceinline__ void cpa16(uint32_t s, const void* g) {
    asm volatile("cp.async.cg.shared.global [%0], [%1], 16;" :: "r"(s), "l"(g));
}
__device__ __forceinline__ void cpa_commit() {
    asm volatile("cp.async.commit_group;" ::: "memory");
}
__device__ __forceinline__ void cpa_wait0() {
    asm volatile("cp.async.wait_group 0;" ::: "memory");
}
__device__ __forceinline__ void ldsm4(uint32_t a, uint32_t* r) {
    asm volatile("ldmatrix.sync.aligned.m8n8.x4.shared.b16 {%0,%1,%2,%3}, [%4];"
                 : "=r"(r[0]), "=r"(r[1]), "=r"(r[2]), "=r"(r[3]) : "r"(a));
}
__device__ __forceinline__ void mma_bf16(float* d, const uint32_t* a,
                                         const uint32_t* b) {
    asm volatile(
        "mma.sync.aligned.m16n8k16.row.col.f32.bf16.bf16.f32 "
        "{%0,%1,%2,%3}, {%4,%5,%6,%7}, {%8,%9}, {%0,%1,%2,%3};"
        : "+f"(d[0]), "+f"(d[1]), "+f"(d[2]), "+f"(d[3])
        : "r"(a[0]), "r"(a[1]), "r"(a[2]), "r"(a[3]), "r"(b[0]), "r"(b[1]));
}
__device__ __forceinline__ void split_pack(float x, float y,
                                           uint32_t& hi, uint32_t& lo) {
    __nv_bfloat16 xh = __float2bfloat16_rn(x);
    __nv_bfloat16 yh = __float2bfloat16_rn(y);
    __nv_bfloat16 xl = __float2bfloat16_rn(x - __bfloat162float(xh));
    __nv_bfloat16 yl = __float2bfloat16_rn(y - __bfloat162float(yh));
    hi = (uint32_t)__bfloat16_as_ushort(xh) |
         ((uint32_t)__bfloat16_as_ushort(yh) << 16);
    lo = (uint32_t)__bfloat16_as_ushort(xl) |
         ((uint32_t)__bfloat16_as_ushort(yl) << 16);
}

// ---------------- pre-pass: K/V fp32 -> bf16 hi/lo tile blocks ----------------
__global__ __launch_bounds__(512)
void sanet_prepass(const float* __restrict__ Ksrc, const float* __restrict__ Vsrc)
{
    const int kt = blockIdx.x, b = blockIdx.y, tid = threadIdx.x;
    char* dst = g_kv + (size_t)(b * NKT + kt) * BUF_SZ;
    const float* Kg = Ksrc + (size_t)b * 64 * HW + kt * 128;
    const float* Vg = Vsrc + (size_t)b * 64 * HW + kt * 128;

    {   // K -> [k][c] planes (transpose), 144B rows
        const int k = tid & 127, c0 = (tid >> 7) * 16;
        float f[16];
        uint32_t h[8], l[8];
        #pragma unroll
        for (int j = 0; j < 16; ++j) f[j] = Kg[(size_t)(c0 + j) * HW + k];
        #pragma unroll
        for (int j = 0; j < 8; ++j) split_pack(f[2 * j], f[2 * j + 1], h[j], l[j]);
        char* d = dst + k * 144 + c0 * 2;
        *(uint4*)(d)                = make_uint4(h[0], h[1], h[2], h[3]);
        *(uint4*)(d + 16)           = make_uint4(h[4], h[5], h[6], h[7]);
        *(uint4*)(d + KPLANE)       = make_uint4(l[0], l[1], l[2], l[3]);
        *(uint4*)(d + KPLANE + 16)  = make_uint4(l[4], l[5], l[6], l[7]);
    }
    {   // V -> [c][k] planes (no transpose), 272B rows
        const int c = tid >> 3, kq = (tid & 7) * 16;
        float f[16];
        uint32_t h[8], l[8];
        #pragma unroll
        for (int j = 0; j < 4; ++j)
            *(float4*)(f + 4 * j) = *(const float4*)(Vg + (size_t)c * HW + kq + 4 * j);
        #pragma unroll
        for (int j = 0; j < 8; ++j) split_pack(f[2 * j], f[2 * j + 1], h[j], l[j]);
        char* d = dst + OFF_VHI + c * 272 + kq * 2;
        *(uint4*)(d)                = make_uint4(h[0], h[1], h[2], h[3]);
        *(uint4*)(d + 16)           = make_uint4(h[4], h[5], h[6], h[7]);
        *(uint4*)(d + VPLANE)       = make_uint4(l[0], l[1], l[2], l[3]);
        *(uint4*)(d + VPLANE + 16)  = make_uint4(l[4], l[5], l[6], l[7]);
    }
}

// ---------------- main kernel ----------------
__global__ __launch_bounds__(NT, 1)
void sanet_main(const float* __restrict__ content, float* __restrict__ out)
{
    extern __shared__ __align__(16) char smc[];
    const uint32_t sb = smem_u32(smc);

    const int tid   = threadIdx.x;
    const int wid   = tid >> 5;
    const int lane  = tid & 31;
    const int qblk  = wid & 7;
    const int khalf = wid >> 3;
    const int g     = lane >> 2;
    const int t     = lane & 3;
    const int b     = blockIdx.y;
    const int q0    = blockIdx.x * BQ;

    const float* Qg = content + (size_t)b * 64 * HW;
    float* outg     = out     + (size_t)b * 128 * HW;
    const char* kvb = g_kv + (size_t)b * NKT * BUF_SZ;

    const uint32_t laneK = (uint32_t)(lane & 7) * 144u +
                           (uint32_t)((lane >> 3) & 1) * 16u +
                           (uint32_t)((lane >> 4) & 1) * (uint32_t)KPLANE;
    const uint32_t laneV = (uint32_t)(lane & 7) * 272u +
                           (uint32_t)((lane >> 3) & 1) * 16u +
                           (uint32_t)((lane >> 4) & 1) * (uint32_t)VPLANE;

    // ---- prologue: stage Q fp32 into buf0 area ----
    float* stQ = (float*)smc;   // [64c][128q] fp32, 32 KB (before tile 0 load)
    #pragma unroll
    for (int j = 0; j < 4; ++j) {
        const int idx = tid + 512 * j;
        const int c = idx >> 5, kc = idx & 31;
        cpa16(sb + c * 512 + kc * 16, Qg + (size_t)c * HW + q0 + kc * 4);
    }
    cpa_commit();
    cpa_wait0();
    __syncthreads();

    {   // content passthrough (coalesced)
        const int q = tid & 127;
        const int c0 = (tid >> 7) * 16;
        #pragma unroll
        for (int j = 0; j < 16; ++j)
            outg[(size_t)(c0 + j) * HW + q0 + q] = stQ[(c0 + j) * 128 + q];
    }

    // ---- persistent Q A-fragments, split in registers from fp32 stage ----
    uint32_t qa_hi[4][4], qa_lo[4][4];
    {
        const int qA = qblk * 16 + g;
        #pragma unroll
        for (int s = 0; s < 4; ++s) {
            const int ch = 16 * s + 2 * t;
            split_pack(stQ[ch * 128 + qA],           stQ[(ch + 1) * 128 + qA],
                       qa_hi[s][0], qa_lo[s][0]);
            split_pack(stQ[ch * 128 + qA + 8],       stQ[(ch + 1) * 128 + qA + 8],
                       qa_hi[s][1], qa_lo[s][1]);
            split_pack(stQ[(ch + 8) * 128 + qA],     stQ[(ch + 9) * 128 + qA],
                       qa_hi[s][2], qa_lo[s][2]);
            split_pack(stQ[(ch + 8) * 128 + qA + 8], stQ[(ch + 9) * 128 + qA + 8],
                       qa_hi[s][3], qa_lo[s][3]);
        }
    }
    __syncthreads();   // stage reads done before tile 0 overwrites buf0

    // ---- prime tile 0 ----
    for (int j = tid; j < NCHUNK; j += NT)
        cpa16(sb + j * 16, kvb + j * 16);
    cpa_commit();
    cpa_wait0();
    __syncthreads();

    float oAcc[8][4];
    #pragma unroll
    for (int nt = 0; nt < 8; ++nt)
        #pragma unroll
        for (int i = 0; i < 4; ++i) oAcc[nt][i] = 0.0f;
    float l0sum = 0.0f, l1sum = 0.0f;

    for (int kt = 0; kt < NKT; ++kt) {
        // prefetch tile kt+1 into the other buffer (overlaps the GEMMs)
        if (kt + 1 < NKT) {
            const uint32_t dst = sb + (uint32_t)((kt + 1) & 1) * BUF_SZ;
            const char* src = kvb + (size_t)(kt + 1) * BUF_SZ;
            for (int j = tid; j < NCHUNK; j += NT)
                cpa16(dst + j * 16, src + j * 16);
            cpa_commit();
        }

        const uint32_t bufb = sb + (uint32_t)(kt & 1) * BUF_SZ;
        const uint32_t kaddr = bufb + (uint32_t)khalf * (64u * 144u) + laneK;
        const uint32_t vaddr = bufb + OFF_VHI + (uint32_t)khalf * 128u + laneV;

        // ---- GEMM1: S[16q x 64k] = Q.K^T (3-term bf16 split) ----
        float sAcc[8][4];
        #pragma unroll
        for (int nt = 0; nt < 8; ++nt)
            #pragma unroll
            for (int i = 0; i < 4; ++i) sAcc[nt][i] = 0.0f;

        #pragma unroll
        for (int s = 0; s < 4; ++s) {
            #pragma unroll
            for (int np = 0; np < 4; ++np) {
                uint32_t ra[4], rb[4];
                ldsm4(kaddr + (2 * np) * 1152u + s * 32u, ra);
                ldsm4(kaddr + (2 * np + 1) * 1152u + s * 32u, rb);
                mma_bf16(sAcc[2 * np],     qa_hi[s], ra);
                mma_bf16(sAcc[2 * np + 1], qa_hi[s], rb);
                mma_bf16(sAcc[2 * np],     qa_hi[s], ra + 2);
                mma_bf16(sAcc[2 * np + 1], qa_hi[s], rb + 2);
                mma_bf16(sAcc[2 * np],     qa_lo[s], ra);
                mma_bf16(sAcc[2 * np + 1], qa_lo[s], rb);
            }
        }

        // ---- softmax (no max shift) + in-place P fragment build ----
        float* flat = &sAcc[0][0];
        float r0 = 0.0f, r1 = 0.0f;
        #pragma unroll
        for (int s = 0; s < 4; ++s) {
            float p[8];
            #pragma unroll
            for (int i = 0; i < 8; ++i) p[i] = __expf(flat[8 * s + i]);
            r0 += (p[0] + p[1]) + (p[4] + p[5]);
            r1 += (p[2] + p[3]) + (p[6] + p[7]);
            uint32_t h01, l01, h23, l23, h45, l45, h67, l67;
            split_pack(p[0], p[1], h01, l01);
            split_pack(p[2], p[3], h23, l23);
            split_pack(p[4], p[5], h45, l45);
            split_pack(p[6], p[7], h67, l67);
            flat[8 * s + 0] = __uint_as_float(h01);
            flat[8 * s + 1] = __uint_as_float(h23);
            flat[8 * s + 2] = __uint_as_float(h45);
            flat[8 * s + 3] = __uint_as_float(h67);
            flat[8 * s + 4] = __uint_as_float(l01);
            flat[8 * s + 5] = __uint_as_float(l23);
            flat[8 * s + 6] = __uint_as_float(l45);
            flat[8 * s + 7] = __uint_as_float(l67);
        }
        r0 += __shfl_xor_sync(0xffffffffu, r0, 1);
        r0 += __shfl_xor_sync(0xffffffffu, r0, 2);
        r1 += __shfl_xor_sync(0xffffffffu, r1, 1);
        r1 += __shfl_xor_sync(0xffffffffu, r1, 2);
        l0sum += r0;
        l1sum += r1;

        // ---- GEMM2: O[16q x 64c] += P.V^T (partial over this key half) ----
        #pragma unroll
        for (int s = 0; s < 4; ++s) {
            uint32_t ah[4], al[4];
            #pragma unroll
            for (int i = 0; i < 4; ++i) {
                ah[i] = __float_as_uint(flat[8 * s + i]);
                al[i] = __float_as_uint(flat[8 * s + 4 + i]);
            }
            #pragma unroll
            for (int np = 0; np < 4; ++np) {
                uint32_t ra[4], rb[4];
                ldsm4(vaddr + (2 * np) * 2176u + s * 32u, ra);
                ldsm4(vaddr + (2 * np + 1) * 2176u + s * 32u, rb);
                mma_bf16(oAcc[2 * np],     ah, ra);
                mma_bf16(oAcc[2 * np + 1], ah, rb);
                mma_bf16(oAcc[2 * np],     ah, ra + 2);
                mma_bf16(oAcc[2 * np + 1], ah, rb + 2);
                mma_bf16(oAcc[2 * np],     al, ra);
                mma_bf16(oAcc[2 * np + 1], al, rb);
            }
        }

        if (kt + 1 < NKT) cpa_wait0();
        __syncthreads();   // all reads of buf[kt&1] done; tile kt+1 visible
    }

    // ---- epilogue: pair-reduce khalf partials via SMEM, normalize, store ----
    float* redO = (float*)smc;             // 8 warps * 32 lanes * 32 floats
    float* redL = (float*)(smc + 32768);
    if (khalf == 1) {
        float* dst = redO + (qblk * 32 + lane) * 32;
        #pragma unroll
        for (int nt = 0; nt < 8; ++nt)
            #pragma unroll
            for (int i = 0; i < 4; ++i) dst[nt * 4 + i] = oAcc[nt][i];
        redL[(qblk * 32 + lane) * 2 + 0] = l0sum;
        redL[(qblk * 32 + lane) * 2 + 1] = l1sum;
    }
    __syncthreads();
    if (khalf == 0) {
        const float* src = redO + (qblk * 32 + lane) * 32;
        const float inv0 = 1.0f / (l0sum + redL[(qblk * 32 + lane) * 2 + 0]);
        const float inv1 = 1.0f / (l1sum + redL[(qblk * 32 + lane) * 2 + 1]);
        const int qa = q0 + qblk * 16 + g;
        const int qb = qa + 8;
        #pragma unroll
        for (int nt = 0; nt < 8; ++nt) {
            const int c = nt * 8 + 2 * t;
            outg[(size_t)(64 + c) * HW + qa] = (oAcc[nt][0] + src[nt * 4 + 0]) * inv0;
            outg[(size_t)(65 + c) * HW + qa] = (oAcc[nt][1] + src[nt * 4 + 1]) * inv0;
            outg[(size_t)(64 + c) * HW + qb] = (oAcc[nt][2] + src[nt * 4 + 2]) * inv1;
            outg[(size_t)(65 + c) * HW + qb] = (oAcc[nt][3] + src[nt * 4 + 3]) * inv1;
        }
    }
}

extern "C" void kernel_launch(void* const* d_in, const int* in_sizes, int n_in,
                              void* d_out, int out_size)
{
    const float* content   = (const float*)d_in[0];
    const float* content_s = (const float*)d_in[1];
    const float* style     = (const float*)d_in[2];
    float* out = (float*)d_out;

    cudaFuncSetAttribute(sanet_main, cudaFuncAttributeMaxDynamicSharedMemorySize,
                         SMEM_BYTES);

    dim3 pgrid(NKT, 4);
    sanet_prepass<<<pgrid, 512>>>(content_s, style);

    dim3 grid(HW / BQ, 4);   // 128 CTAs
    sanet_main<<<grid, NT, SMEM_BYTES>>>(content, out);
}